// round 2
// baseline (speedup 1.0000x reference)
#include <cuda_runtime.h>
#include <math.h>

#define BB 256      // batch
#define TT 512      // time
#define NPOS 128
#define NACT 32
#define DIN 160     // NPOS + NACT
#define HH 512      // hidden
#define G4 2048     // 4*H
#define KTOT 672    // HH + DIN : k<512 -> recurrent (h, W_hh), k>=512 -> input (x, W_ih)

// ---- persistent scratch (device globals: the allowed scratch mechanism) ----
__device__ float g_WT[KTOT * G4];       // WT[k][g]  (5.5 MB)  combined W_hh^T / W_ih^T
__device__ float g_xT[TT * DIN * BB];   // xT[t][d][b] (84 MB) transposed inputs
__device__ float g_h[2][HH * BB];       // h[j][b] ping-pong
__device__ float g_c[HH * BB];          // c[j][b]
__device__ float g_bias[G4];            // b_ih + b_hh

// ------------------------------------------------------------------ init ----
__global__ void k_bias(const float* __restrict__ b_ih, const float* __restrict__ b_hh) {
    int i = blockIdx.x * blockDim.x + threadIdx.x;
    if (i < G4) g_bias[i] = b_ih[i] + b_hh[i];
}

__global__ void k_out_init(float* __restrict__ out, const float* __restrict__ b_out) {
    int i = blockIdx.x * blockDim.x + threadIdx.x;
    if (i < BB * TT) out[i] = b_out[0];
}

__global__ void k_wt(const float* __restrict__ W_hh, const float* __restrict__ W_ih) {
    int idx = blockIdx.x * blockDim.x + threadIdx.x;
    if (idx >= KTOT * G4) return;
    int k = idx / G4;
    int g = idx - k * G4;
    float v = (k < HH) ? W_hh[g * HH + k] : W_ih[g * DIN + (k - HH)];
    g_WT[idx] = v;
}

// tiled transpose of concat(obs, act): x[b][t][d] -> xT[t][d][b]
__global__ void k_xt(const float* __restrict__ obs, const float* __restrict__ act) {
    __shared__ float tile[32][33];
    int t  = blockIdx.x;          // 0..511
    int d0 = blockIdx.y * 32;     // 0..4 tiles of d (160 = 5*32)
    int b0 = blockIdx.z * 32;     // 0..7 tiles of b
    int tx = threadIdx.x;         // 0..31
    int ty = threadIdx.y;         // 0..7
#pragma unroll
    for (int i = 0; i < 4; ++i) {
        int bl = ty + i * 8;
        int b = b0 + bl;
        int d = d0 + tx;
        float v;
        if (d < NPOS) v = obs[((long)b * TT + t) * NPOS + d];
        else          v = act[((long)b * TT + t) * NACT + (d - NPOS)];
        tile[bl][tx] = v;
    }
    __syncthreads();
#pragma unroll
    for (int i = 0; i < 4; ++i) {
        int dl = ty + i * 8;
        int d = d0 + dl;
        int b = b0 + tx;
        g_xT[((long)t * DIN + d) * BB + b] = tile[tx][dl];
    }
}

__global__ void k_state(const float* __restrict__ h0, const float* __restrict__ c0) {
    int idx = blockIdx.x * blockDim.x + threadIdx.x;
    if (idx >= HH * BB) return;
    int j = idx >> 8;          // / BB
    int b = idx & 255;
    g_h[0][idx] = h0[b * HH + j];
    g_c[idx]    = c0[b * HH + j];
}

// ------------------------------------------------------------------ step ----
// grid (32 j-tiles, 4 b-tiles), 256 threads.
// CTA owns hidden slice j0..j0+15 (all 4 gate quadrants => 64 gate rows)
// and batch slice b0..b0+63.  M=64 gate rows, N=64 batch, K=672.
__global__ void __launch_bounds__(256, 1)
step_kernel(int t, int par,
            const float* __restrict__ W_out,
            float* __restrict__ out) {
    // shared: first 32x68 = W chunk [k][m], second 32x68 = src chunk [k][n];
    // reused afterwards as gate buffer [64][68].
    __shared__ float smem[2 * 32 * 68];

    const int j0 = blockIdx.x * 16;
    const int b0 = blockIdx.y * 64;
    const int tid = threadIdx.x;
    const int tx = tid & 15;        // n direction
    const int ty = tid >> 4;        // m direction

    const float* __restrict__ hin = g_h[par];
    float* __restrict__ hout = g_h[par ^ 1];

    float acc[4][4];
#pragma unroll
    for (int i = 0; i < 4; ++i)
#pragma unroll
        for (int j = 0; j < 4; ++j) acc[i][j] = 0.0f;

    for (int kc = 0; kc < 21; ++kc) {
        const int k0 = kc * 32;
        const float* __restrict__ wrow = g_WT + (long)k0 * G4;
        const float* __restrict__ bsrc = (kc < 16)
            ? (hin + (long)k0 * BB + b0)
            : (g_xT + ((long)t * DIN + (k0 - HH)) * BB + b0);

        // load W chunk [32 k][64 m] and source chunk [32 k][64 n]
#pragma unroll
        for (int i = 0; i < 8; ++i) {
            int idx = tid + i * 256;          // 0..2047
            int kk = idx >> 6;
            int mi = idx & 63;
            int g = ((mi >> 4) << 9) + j0 + (mi & 15);  // quadrant*512 + j0 + jj
            smem[kk * 68 + mi] = wrow[kk * G4 + g];
            smem[32 * 68 + kk * 68 + mi] = bsrc[kk * BB + mi];
        }
        __syncthreads();

#pragma unroll
        for (int kk = 0; kk < 32; ++kk) {
            float4 av = *(const float4*)&smem[kk * 68 + ty * 4];
            float4 bv = *(const float4*)&smem[32 * 68 + kk * 68 + tx * 4];
            acc[0][0] += av.x * bv.x; acc[0][1] += av.x * bv.y;
            acc[0][2] += av.x * bv.z; acc[0][3] += av.x * bv.w;
            acc[1][0] += av.y * bv.x; acc[1][1] += av.y * bv.y;
            acc[1][2] += av.y * bv.z; acc[1][3] += av.y * bv.w;
            acc[2][0] += av.z * bv.x; acc[2][1] += av.z * bv.y;
            acc[2][2] += av.z * bv.z; acc[2][3] += av.z * bv.w;
            acc[3][0] += av.w * bv.x; acc[3][1] += av.w * bv.y;
            acc[3][2] += av.w * bv.z; acc[3][3] += av.w * bv.w;
        }
        __syncthreads();
    }

    // dump gates to shared: SG[m][n], m = quadrant*16 + jj
#pragma unroll
    for (int i = 0; i < 4; ++i) {
        int m = ty * 4 + i;
#pragma unroll
        for (int j = 0; j < 4; ++j) {
            smem[m * 68 + tx * 4 + j] = acc[i][j];
        }
    }
    __syncthreads();

    // elementwise LSTM cell + output projection partial
    const int n = tid & 63;           // same batch column for all 4 iterations
    const int b = b0 + n;
    float yp = 0.0f;
#pragma unroll
    for (int i = 0; i < 4; ++i) {
        int jj = (tid >> 6) + i * 4;  // 0..15
        int j = j0 + jj;
        float gi = smem[(jj)      * 68 + n] + g_bias[j];
        float gf = smem[(16 + jj) * 68 + n] + g_bias[HH + j];
        float gg = smem[(32 + jj) * 68 + n] + g_bias[2 * HH + j];
        float go = smem[(48 + jj) * 68 + n] + g_bias[3 * HH + j];
        float iv = 1.0f / (1.0f + expf(-gi));
        float fv = 1.0f / (1.0f + expf(-gf));
        float gv = tanhf(gg);
        float ov = 1.0f / (1.0f + expf(-go));
        float c = g_c[j * BB + b];
        float cn = fv * c + iv * gv;
        g_c[j * BB + b] = cn;
        float hn = ov * tanhf(cn);
        hout[j * BB + b] = hn;
        yp += hn * W_out[j];
    }
    __syncthreads();          // gates fully consumed
    smem[tid] = yp;           // 256 partials
    __syncthreads();
    if (tid < 64) {
        float y = smem[tid] + smem[tid + 64] + smem[tid + 128] + smem[tid + 192];
        atomicAdd(&out[(b0 + tid) * TT + t], y);   // out pre-initialized to b_out
    }
}

// ---------------------------------------------------------------- launch ----
extern "C" void kernel_launch(void* const* d_in, const int* in_sizes, int n_in,
                              void* d_out, int out_size) {
    const float* obs   = (const float*)d_in[0];
    const float* act   = (const float*)d_in[1];
    const float* W_ih  = (const float*)d_in[2];
    const float* W_hh  = (const float*)d_in[3];
    const float* b_ih  = (const float*)d_in[4];
    const float* b_hh  = (const float*)d_in[5];
    const float* W_out = (const float*)d_in[6];
    const float* b_out = (const float*)d_in[7];
    const float* h0    = (const float*)d_in[8];
    const float* c0    = (const float*)d_in[9];
    float* out = (float*)d_out;

    k_bias<<<8, 256>>>(b_ih, b_hh);
    k_out_init<<<(BB * TT) / 256, 256>>>(out, b_out);
    k_wt<<<(KTOT * G4) / 256, 256>>>(W_hh, W_ih);
    k_xt<<<dim3(TT, DIN / 32, BB / 32), dim3(32, 8)>>>(obs, act);
    k_state<<<(HH * BB) / 256, 256>>>(h0, c0);

    for (int t = 0; t < TT; ++t) {
        step_kernel<<<dim3(HH / 16, BB / 64), 256>>>(t, t & 1, W_out, out);
    }
}

// round 3
// speedup vs baseline: 1.0007x; 1.0007x over previous
#include <cuda_runtime.h>
#include <math.h>

#define BB 256      // batch
#define TT 512      // time
#define NPOS 128
#define NACT 32
#define DIN 160     // NPOS + NACT
#define HH 512      // hidden
#define G4 2048     // 4*H
#define KTOT 672    // HH + DIN : k<512 -> recurrent (h, W_hh), k>=512 -> input (x, W_ih)

// ---- persistent scratch (device globals: the allowed scratch mechanism) ----
__device__ float g_WT[KTOT * G4];       // WT[k][g]  (5.5 MB)  combined W_hh^T / W_ih^T
__device__ float g_xT[TT * DIN * BB];   // xT[t][d][b] (84 MB) transposed inputs
__device__ float g_h[2][HH * BB];       // h[j][b] ping-pong
__device__ float g_c[HH * BB];          // c[j][b]
__device__ float g_bias[G4];            // b_ih + b_hh

// ------------------------------------------------------------------ init ----
__global__ void k_bias(const float* __restrict__ b_ih, const float* __restrict__ b_hh) {
    int i = blockIdx.x * blockDim.x + threadIdx.x;
    if (i < G4) g_bias[i] = b_ih[i] + b_hh[i];
}

__global__ void k_out_init(float* __restrict__ out, const float* __restrict__ b_out) {
    int i = blockIdx.x * blockDim.x + threadIdx.x;
    if (i < BB * TT) out[i] = b_out[0];
}

__global__ void k_wt(const float* __restrict__ W_hh, const float* __restrict__ W_ih) {
    int idx = blockIdx.x * blockDim.x + threadIdx.x;
    if (idx >= KTOT * G4) return;
    int k = idx / G4;
    int g = idx - k * G4;
    float v = (k < HH) ? W_hh[g * HH + k] : W_ih[g * DIN + (k - HH)];
    g_WT[idx] = v;
}

// tiled transpose of concat(obs, act): x[b][t][d] -> xT[t][d][b]
__global__ void k_xt(const float* __restrict__ obs, const float* __restrict__ act) {
    __shared__ float tile[32][33];
    int t  = blockIdx.x;          // 0..511
    int d0 = blockIdx.y * 32;     // 0..4 tiles of d (160 = 5*32)
    int b0 = blockIdx.z * 32;     // 0..7 tiles of b
    int tx = threadIdx.x;         // 0..31
    int ty = threadIdx.y;         // 0..7
#pragma unroll
    for (int i = 0; i < 4; ++i) {
        int bl = ty + i * 8;
        int b = b0 + bl;
        int d = d0 + tx;
        float v;
        if (d < NPOS) v = obs[((long)b * TT + t) * NPOS + d];
        else          v = act[((long)b * TT + t) * NACT + (d - NPOS)];
        tile[bl][tx] = v;
    }
    __syncthreads();
#pragma unroll
    for (int i = 0; i < 4; ++i) {
        int dl = ty + i * 8;
        int d = d0 + dl;
        int b = b0 + tx;
        g_xT[((long)t * DIN + d) * BB + b] = tile[tx][dl];
    }
}

__global__ void k_state(const float* __restrict__ h0, const float* __restrict__ c0) {
    int idx = blockIdx.x * blockDim.x + threadIdx.x;
    if (idx >= HH * BB) return;
    int j = idx >> 8;          // / BB
    int b = idx & 255;
    g_h[0][idx] = h0[b * HH + j];
    g_c[idx]    = c0[b * HH + j];
}

// ------------------------------------------------------------------ step ----
// grid (32 j-tiles, 4 b-tiles), 256 threads.
// CTA owns hidden slice j0..j0+15 (all 4 gate quadrants => 64 gate rows)
// and batch slice b0..b0+63.  M=64 gate rows, N=64 batch, K=672.
__global__ void __launch_bounds__(256, 1)
step_kernel(int t, int par,
            const float* __restrict__ W_out,
            float* __restrict__ out) {
    // shared: first 32x68 = W chunk [k][m], second 32x68 = src chunk [k][n];
    // reused afterwards as gate buffer [64][68].
    __shared__ float smem[2 * 32 * 68];

    const int j0 = blockIdx.x * 16;
    const int b0 = blockIdx.y * 64;
    const int tid = threadIdx.x;
    const int tx = tid & 15;        // n direction
    const int ty = tid >> 4;        // m direction

    const float* __restrict__ hin = g_h[par];
    float* __restrict__ hout = g_h[par ^ 1];

    float acc[4][4];
#pragma unroll
    for (int i = 0; i < 4; ++i)
#pragma unroll
        for (int j = 0; j < 4; ++j) acc[i][j] = 0.0f;

    for (int kc = 0; kc < 21; ++kc) {
        const int k0 = kc * 32;
        const float* __restrict__ wrow = g_WT + (long)k0 * G4;
        const float* __restrict__ bsrc = (kc < 16)
            ? (hin + (long)k0 * BB + b0)
            : (g_xT + ((long)t * DIN + (k0 - HH)) * BB + b0);

        // load W chunk [32 k][64 m] and source chunk [32 k][64 n]
#pragma unroll
        for (int i = 0; i < 8; ++i) {
            int idx = tid + i * 256;          // 0..2047
            int kk = idx >> 6;
            int mi = idx & 63;
            int g = ((mi >> 4) << 9) + j0 + (mi & 15);  // quadrant*512 + j0 + jj
            smem[kk * 68 + mi] = wrow[kk * G4 + g];
            smem[32 * 68 + kk * 68 + mi] = bsrc[kk * BB + mi];
        }
        __syncthreads();

#pragma unroll
        for (int kk = 0; kk < 32; ++kk) {
            float4 av = *(const float4*)&smem[kk * 68 + ty * 4];
            float4 bv = *(const float4*)&smem[32 * 68 + kk * 68 + tx * 4];
            acc[0][0] += av.x * bv.x; acc[0][1] += av.x * bv.y;
            acc[0][2] += av.x * bv.z; acc[0][3] += av.x * bv.w;
            acc[1][0] += av.y * bv.x; acc[1][1] += av.y * bv.y;
            acc[1][2] += av.y * bv.z; acc[1][3] += av.y * bv.w;
            acc[2][0] += av.z * bv.x; acc[2][1] += av.z * bv.y;
            acc[2][2] += av.z * bv.z; acc[2][3] += av.z * bv.w;
            acc[3][0] += av.w * bv.x; acc[3][1] += av.w * bv.y;
            acc[3][2] += av.w * bv.z; acc[3][3] += av.w * bv.w;
        }
        __syncthreads();
    }

    // dump gates to shared: SG[m][n], m = quadrant*16 + jj
#pragma unroll
    for (int i = 0; i < 4; ++i) {
        int m = ty * 4 + i;
#pragma unroll
        for (int j = 0; j < 4; ++j) {
            smem[m * 68 + tx * 4 + j] = acc[i][j];
        }
    }
    __syncthreads();

    // elementwise LSTM cell + output projection partial
    const int n = tid & 63;           // same batch column for all 4 iterations
    const int b = b0 + n;
    float yp = 0.0f;
#pragma unroll
    for (int i = 0; i < 4; ++i) {
        int jj = (tid >> 6) + i * 4;  // 0..15
        int j = j0 + jj;
        float gi = smem[(jj)      * 68 + n] + g_bias[j];
        float gf = smem[(16 + jj) * 68 + n] + g_bias[HH + j];
        float gg = smem[(32 + jj) * 68 + n] + g_bias[2 * HH + j];
        float go = smem[(48 + jj) * 68 + n] + g_bias[3 * HH + j];
        float iv = 1.0f / (1.0f + expf(-gi));
        float fv = 1.0f / (1.0f + expf(-gf));
        float gv = tanhf(gg);
        float ov = 1.0f / (1.0f + expf(-go));
        float c = g_c[j * BB + b];
        float cn = fv * c + iv * gv;
        g_c[j * BB + b] = cn;
        float hn = ov * tanhf(cn);
        hout[j * BB + b] = hn;
        yp += hn * W_out[j];
    }
    __syncthreads();          // gates fully consumed
    smem[tid] = yp;           // 256 partials
    __syncthreads();
    if (tid < 64) {
        float y = smem[tid] + smem[tid + 64] + smem[tid + 128] + smem[tid + 192];
        atomicAdd(&out[(b0 + tid) * TT + t], y);   // out pre-initialized to b_out
    }
}

// ---------------------------------------------------------------- launch ----
extern "C" void kernel_launch(void* const* d_in, const int* in_sizes, int n_in,
                              void* d_out, int out_size) {
    const float* obs   = (const float*)d_in[0];
    const float* act   = (const float*)d_in[1];
    const float* W_ih  = (const float*)d_in[2];
    const float* W_hh  = (const float*)d_in[3];
    const float* b_ih  = (const float*)d_in[4];
    const float* b_hh  = (const float*)d_in[5];
    const float* W_out = (const float*)d_in[6];
    const float* b_out = (const float*)d_in[7];
    const float* h0    = (const float*)d_in[8];
    const float* c0    = (const float*)d_in[9];
    float* out = (float*)d_out;

    k_bias<<<8, 256>>>(b_ih, b_hh);
    k_out_init<<<(BB * TT) / 256, 256>>>(out, b_out);
    k_wt<<<(KTOT * G4) / 256, 256>>>(W_hh, W_ih);
    k_xt<<<dim3(TT, DIN / 32, BB / 32), dim3(32, 8)>>>(obs, act);
    k_state<<<(HH * BB) / 256, 256>>>(h0, c0);

    for (int t = 0; t < TT; ++t) {
        step_kernel<<<dim3(HH / 16, BB / 64), 256>>>(t, t & 1, W_out, out);
    }
}

// round 9
// speedup vs baseline: 1.2300x; 1.2291x over previous
#include <cuda_runtime.h>
#include <stdint.h>
#include <math.h>

#define BB 256      // batch
#define TT 512      // time
#define NPOS 128
#define NACT 32
#define DIN 160     // NPOS + NACT
#define HH 512      // hidden
#define G4 2048     // 4*H
#define KTOT 672    // HH + DIN
#define NCHUNK 21   // KTOT / 32
#define STAGE_F 4352   // floats per pipeline stage: W(32x68) + src(32x68)
#define SMEM_BYTES (4 * STAGE_F * 4)   // 69632 B dynamic smem

// ---- persistent scratch (device globals) ----
__device__ __align__(16) float g_WT[KTOT * G4];       // WT[k][g]
__device__ __align__(16) float g_xT[TT * DIN * BB];   // xT[t][d][b]
__device__ __align__(16) float g_h[2][HH * BB];       // h[j][b] ping-pong
__device__ __align__(16) float g_c[HH * BB];          // c[j][b]
__device__ __align__(16) float g_bias[G4];            // b_ih + b_hh

// ------------------------------------------------------------------ init ----
__global__ void k_bias(const float* __restrict__ b_ih, const float* __restrict__ b_hh) {
    int i = blockIdx.x * blockDim.x + threadIdx.x;
    if (i < G4) g_bias[i] = b_ih[i] + b_hh[i];
}

__global__ void k_out_init(float* __restrict__ out, const float* __restrict__ b_out) {
    int i = blockIdx.x * blockDim.x + threadIdx.x;
    if (i < BB * TT) out[i] = b_out[0];
}

__global__ void k_wt(const float* __restrict__ W_hh, const float* __restrict__ W_ih) {
    int idx = blockIdx.x * blockDim.x + threadIdx.x;
    if (idx >= KTOT * G4) return;
    int k = idx / G4;
    int g = idx - k * G4;
    float v = (k < HH) ? W_hh[g * HH + k] : W_ih[g * DIN + (k - HH)];
    g_WT[idx] = v;
}

// tiled transpose of concat(obs, act): x[b][t][d] -> xT[t][d][b]
__global__ void k_xt(const float* __restrict__ obs, const float* __restrict__ act) {
    __shared__ float tile[32][33];
    int t  = blockIdx.x;
    int d0 = blockIdx.y * 32;
    int b0 = blockIdx.z * 32;
    int tx = threadIdx.x;
    int ty = threadIdx.y;
#pragma unroll
    for (int i = 0; i < 4; ++i) {
        int bl = ty + i * 8;
        int b = b0 + bl;
        int d = d0 + tx;
        float v;
        if (d < NPOS) v = obs[((long)b * TT + t) * NPOS + d];
        else          v = act[((long)b * TT + t) * NACT + (d - NPOS)];
        tile[bl][tx] = v;
    }
    __syncthreads();
#pragma unroll
    for (int i = 0; i < 4; ++i) {
        int dl = ty + i * 8;
        int d = d0 + dl;
        int b = b0 + tx;
        g_xT[((long)t * DIN + d) * BB + b] = tile[tx][dl];
    }
}

__global__ void k_state(const float* __restrict__ h0, const float* __restrict__ c0) {
    int idx = blockIdx.x * blockDim.x + threadIdx.x;
    if (idx >= HH * BB) return;
    int j = idx >> 8;
    int b = idx & 255;
    g_h[0][idx] = h0[b * HH + j];
    g_c[idx]    = c0[b * HH + j];
}

// ------------------------------------------------------------- utilities ----
__device__ __forceinline__ void cp16(uint32_t saddr, const float* g) {
    asm volatile("cp.async.cg.shared.global [%0], [%1], 16;"
                 :: "r"(saddr), "l"(g) : "memory");
}
__device__ __forceinline__ void cp_commit() {
    asm volatile("cp.async.commit_group;" ::: "memory");
}
__device__ __forceinline__ void cp_wait2() {
    asm volatile("cp.async.wait_group 2;" ::: "memory");
}

__device__ __forceinline__ float fsig(float x) {
    return 1.0f / (1.0f + __expf(-x));
}
__device__ __forceinline__ float ftanh(float x) {
    // 1 - 2/(e^{2x}+1): exact at +/-inf, ~1e-6 rel err, single MUFU path
    return 1.0f - 2.0f / (__expf(2.0f * x) + 1.0f);
}

// ------------------------------------------------------------------ step ----
// grid (32 j-tiles, 4 b-tiles), 256 threads.
// CTA: hidden slice j0..j0+15 across all 4 gate quadrants (64 gate rows) x
// batch slice b0..b0+63. M=64, N=64, K=672, 4-stage cp.async pipeline.
__global__ void __launch_bounds__(256, 1)
step_kernel(int t, int par,
            const float* __restrict__ W_out,
            float* __restrict__ out) {
    extern __shared__ float sm[];

    const int j0 = blockIdx.x * 16;
    const int b0 = blockIdx.y * 64;
    const int tid = threadIdx.x;
    const int tx = tid & 15;        // n direction
    const int ty = tid >> 4;        // m direction

    const float* __restrict__ hin = g_h[par];
    float* __restrict__ hout = g_h[par ^ 1];

    uint32_t sbase;
    asm("{ .reg .u64 tt; cvta.to.shared.u64 tt, %1; cvt.u32.u64 %0, tt; }"
        : "=r"(sbase) : "l"(sm));

    // per-thread cp.async slots: slot i covers kk = kk0 + 16*i, 4 floats at m4*4
    const int kk0 = tid >> 4;       // 0..15
    const int m4  = tid & 15;       // float4 index within 64-wide row
    const int gcol = ((m4 >> 2) << 9) + j0 + (m4 & 3) * 4;  // gate column base
    const uint32_t swA0 = (kk0 * 68 + m4 * 4) * 4;
    const uint32_t swA1 = ((kk0 + 16) * 68 + m4 * 4) * 4;
    const uint32_t ssB0 = (2176 + kk0 * 68 + m4 * 4) * 4;
    const uint32_t ssB1 = (2176 + (kk0 + 16) * 68 + m4 * 4) * 4;

    float acc[4][4];
#pragma unroll
    for (int i = 0; i < 4; ++i)
#pragma unroll
        for (int j = 0; j < 4; ++j) acc[i][j] = 0.0f;

    // issue chunk c into stage c&3
    auto issue = [&](int c) {
        const float* __restrict__ wsrc = g_WT + (long)c * 32 * G4;
        const float* __restrict__ bs = (c < 16)
            ? (hin + (long)c * 32 * BB + b0)
            : (g_xT + ((long)t * DIN + (c * 32 - HH)) * BB + b0);
        uint32_t st = sbase + (uint32_t)(c & 3) * (STAGE_F * 4);
        cp16(st + swA0, wsrc + kk0 * G4 + gcol);
        cp16(st + swA1, wsrc + (kk0 + 16) * G4 + gcol);
        cp16(st + ssB0, bs + kk0 * BB + m4 * 4);
        cp16(st + ssB1, bs + (kk0 + 16) * BB + m4 * 4);
    };

    issue(0); cp_commit();
    issue(1); cp_commit();
    issue(2); cp_commit();

#pragma unroll 1
    for (int kc = 0; kc < NCHUNK; ++kc) {
        cp_wait2();            // chunk kc complete (2 newer groups may pend)
        __syncthreads();       // visibility + WAR protection for stage reuse
        if (kc + 3 < NCHUNK) issue(kc + 3);
        cp_commit();           // always commit (empty group near tail)

        const float* __restrict__ bufW = sm + (kc & 3) * STAGE_F;
        const float* __restrict__ bufS = bufW + 2176;
#pragma unroll
        for (int kk = 0; kk < 32; ++kk) {
            float4 av = *(const float4*)&bufW[kk * 68 + ty * 4];
            float4 bv = *(const float4*)&bufS[kk * 68 + tx * 4];
            acc[0][0] += av.x * bv.x; acc[0][1] += av.x * bv.y;
            acc[0][2] += av.x * bv.z; acc[0][3] += av.x * bv.w;
            acc[1][0] += av.y * bv.x; acc[1][1] += av.y * bv.y;
            acc[1][2] += av.y * bv.z; acc[1][3] += av.y * bv.w;
            acc[2][0] += av.z * bv.x; acc[2][1] += av.z * bv.y;
            acc[2][2] += av.z * bv.z; acc[2][3] += av.z * bv.w;
            acc[3][0] += av.w * bv.x; acc[3][1] += av.w * bv.y;
            acc[3][2] += av.w * bv.z; acc[3][3] += av.w * bv.w;
        }
    }
    __syncthreads();   // all compute done before stage 0 is reused for gates

    // dump gates to shared: SG[m][n], m = quadrant*16 + jj
#pragma unroll
    for (int i = 0; i < 4; ++i) {
        int m = ty * 4 + i;
#pragma unroll
        for (int j = 0; j < 4; ++j) {
            sm[m * 68 + tx * 4 + j] = acc[i][j];
        }
    }
    __syncthreads();

    // elementwise LSTM cell + output projection partial
    const int n = tid & 63;
    const int b = b0 + n;
    float yp = 0.0f;
#pragma unroll
    for (int i = 0; i < 4; ++i) {
        int jj = (tid >> 6) + i * 4;  // 0..15
        int j = j0 + jj;
        float gi = sm[(jj)      * 68 + n] + g_bias[j];
        float gf = sm[(16 + jj) * 68 + n] + g_bias[HH + j];
        float gg = sm[(32 + jj) * 68 + n] + g_bias[2 * HH + j];
        float go = sm[(48 + jj) * 68 + n] + g_bias[3 * HH + j];
        float iv = fsig(gi);
        float fv = fsig(gf);
        float gv = ftanh(gg);
        float ov = fsig(go);
        float c = g_c[j * BB + b];
        float cn = fv * c + iv * gv;
        g_c[j * BB + b] = cn;
        float hn = ov * ftanh(cn);
        hout[j * BB + b] = hn;
        yp += hn * W_out[j];
    }
    __syncthreads();
    sm[tid] = yp;
    __syncthreads();
    if (tid < 64) {
        float y = sm[tid] + sm[tid + 64] + sm[tid + 128] + sm[tid + 192];
        atomicAdd(&out[(b0 + tid) * TT + t], y);
    }
}

// ---------------------------------------------------------------- launch ----
extern "C" void kernel_launch(void* const* d_in, const int* in_sizes, int n_in,
                              void* d_out, int out_size) {
    const float* obs   = (const float*)d_in[0];
    const float* act   = (const float*)d_in[1];
    const float* W_ih  = (const float*)d_in[2];
    const float* W_hh  = (const float*)d_in[3];
    const float* b_ih  = (const float*)d_in[4];
    const float* b_hh  = (const float*)d_in[5];
    const float* W_out = (const float*)d_in[6];
    const float* b_out = (const float*)d_in[7];
    const float* h0    = (const float*)d_in[8];
    const float* c0    = (const float*)d_in[9];
    float* out = (float*)d_out;

    cudaFuncSetAttribute(step_kernel,
                         cudaFuncAttributeMaxDynamicSharedMemorySize, SMEM_BYTES);

    k_bias<<<8, 256>>>(b_ih, b_hh);
    k_out_init<<<(BB * TT) / 256, 256>>>(out, b_out);
    k_wt<<<(KTOT * G4) / 256, 256>>>(W_hh, W_ih);
    k_xt<<<dim3(TT, DIN / 32, BB / 32), dim3(32, 8)>>>(obs, act);
    k_state<<<(HH * BB) / 256, 256>>>(h0, c0);

    for (int t = 0; t < TT; ++t) {
        step_kernel<<<dim3(HH / 16, BB / 64), 256, SMEM_BYTES>>>(t, t & 1, W_out, out);
    }
}